// round 4
// baseline (speedup 1.0000x reference)
#include <cuda_runtime.h>

#define B_ 64
#define S_ 8192
#define E_ 32
#define H_ 64

// Scratch (no allocs allowed): q tensor (64 MB) + per-(b,f) sum of squares.
__device__ __align__(16) static float g_q[(size_t)B_ * S_ * E_];
__device__ static float g_sumsq[B_ * E_];

__global__ void k_zero_sumsq() {
    int i = blockIdx.x * blockDim.x + threadIdx.x;
    if (i < B_ * E_) g_sumsq[i] = 0.0f;
}

__device__ __forceinline__ float silu_f(float v) {
    // v * sigmoid(v); fast-math error ~1e-7 rel, far under the 1e-3 budget
    return v * __fdividef(1.0f, 1.0f + __expf(-v));
}

// ---------- Pass A: q = silu(x @ Qw^T), accumulate sum_s q^2 per (b,f) ----------
template <int TA>
__global__ __launch_bounds__(256) void k_passA(const float* __restrict__ x,
                                               const float* __restrict__ Qw) {
    const int b = blockIdx.y;
    __shared__ __align__(16) float Qs[E_ * E_];  // [f][e]
    __shared__ float ssum[E_];
    for (int i = threadIdx.x; i < E_ * E_; i += 256) Qs[i] = Qw[i];
    if (threadIdx.x < E_) ssum[threadIdx.x] = 0.0f;
    __syncthreads();

    float acc2[E_];
#pragma unroll
    for (int f = 0; f < E_; ++f) acc2[f] = 0.0f;

    const int s0 = blockIdx.x * (256 * TA);
    for (int t = 0; t < TA; ++t) {
        const int s = s0 + t * 256 + threadIdx.x;
        const float4* xp = reinterpret_cast<const float4*>(x + ((size_t)b * S_ + s) * E_);
        float4 xv[E_ / 4];
#pragma unroll
        for (int i = 0; i < E_ / 4; ++i) xv[i] = xp[i];

        float4* qp = reinterpret_cast<float4*>(g_q + ((size_t)b * S_ + s) * E_);
#pragma unroll
        for (int fg = 0; fg < E_ / 4; ++fg) {
            float qt[4];
#pragma unroll
            for (int fi = 0; fi < 4; ++fi) {
                const int f = fg * 4 + fi;
                const float4* wp = reinterpret_cast<const float4*>(Qs + f * E_);
                float a = 0.0f;
#pragma unroll
                for (int i = 0; i < E_ / 4; ++i) {
                    float4 w = wp[i];  // LDS.128 broadcast (all lanes same addr)
                    a = fmaf(w.x, xv[i].x, a);
                    a = fmaf(w.y, xv[i].y, a);
                    a = fmaf(w.z, xv[i].z, a);
                    a = fmaf(w.w, xv[i].w, a);
                }
                float qq = silu_f(a);
                qt[fi] = qq;
                acc2[f] = fmaf(qq, qq, acc2[f]);
            }
            qp[fg] = make_float4(qt[0], qt[1], qt[2], qt[3]);
        }
    }

    // Block-level reduction of per-thread partials, then one global atomic per (b,f)
#pragma unroll
    for (int f = 0; f < E_; ++f) atomicAdd(&ssum[f], acc2[f]);
    __syncthreads();
    if (threadIdx.x < E_) atomicAdd(&g_sumsq[b * E_ + threadIdx.x], ssum[threadIdx.x]);
}

// ---------- Pass B: normalize (folded into W1), per-token MLP, write out ----------
template <int TB>
__global__ __launch_bounds__(256) void k_passB(const float* __restrict__ W1,
                                               const float* __restrict__ b1,
                                               const float* __restrict__ W2,
                                               const float* __restrict__ b2,
                                               float* __restrict__ out) {
    const int b = blockIdx.y;
    const int tid = threadIdx.x;
    __shared__ __align__(16) float W1s[H_ * E_];  // [j][e], pre-scaled by 1/norm[e]
    __shared__ __align__(16) float W2s[E_ * H_];  // [e][j]
    __shared__ float b1s[H_];
    __shared__ float b2s[E_];
    __shared__ float rsq[E_];

    if (tid < E_) {
        float n = sqrtf(g_sumsq[b * E_ + tid]);
        rsq[tid] = 1.0f / fmaxf(n, 1e-12f);
        b2s[tid] = b2[b * E_ + tid];
    }
    if (tid < H_) b1s[tid] = b1[b * H_ + tid];
    __syncthreads();  // rsq ready before scaled W1 load

    for (int i = tid; i < H_ * E_; i += 256)
        W1s[i] = W1[(size_t)b * H_ * E_ + i] * rsq[i & (E_ - 1)];
    for (int i = tid; i < E_ * H_; i += 256)
        W2s[i] = W2[(size_t)b * E_ * H_ + i];
    __syncthreads();

    const int s0 = blockIdx.x * (256 * TB);
    for (int t = 0; t < TB; ++t) {
        const int s = s0 + t * 256 + tid;
        const float4* qp = reinterpret_cast<const float4*>(g_q + ((size_t)b * S_ + s) * E_);
        float4 qv[E_ / 4];
#pragma unroll
        for (int i = 0; i < E_ / 4; ++i) qv[i] = qp[i];

        float h[H_];
#pragma unroll
        for (int j = 0; j < H_; ++j) {
            const float4* wp = reinterpret_cast<const float4*>(W1s + j * E_);
            float a = b1s[j];
#pragma unroll
            for (int i = 0; i < E_ / 4; ++i) {
                float4 w = wp[i];
                a = fmaf(w.x, qv[i].x, a);
                a = fmaf(w.y, qv[i].y, a);
                a = fmaf(w.z, qv[i].z, a);
                a = fmaf(w.w, qv[i].w, a);
            }
            h[j] = silu_f(a);
        }

        float4* op = reinterpret_cast<float4*>(out + ((size_t)b * S_ + s) * E_);
#pragma unroll
        for (int eg = 0; eg < E_ / 4; ++eg) {
            float o[4];
#pragma unroll
            for (int ei = 0; ei < 4; ++ei) {
                const int e = eg * 4 + ei;
                const float* wp = W2s + e * H_;
                float a = b2s[e];
#pragma unroll
                for (int j = 0; j < H_; j += 4) {
                    float4 w = *reinterpret_cast<const float4*>(wp + j);
                    a = fmaf(w.x, h[j + 0], a);
                    a = fmaf(w.y, h[j + 1], a);
                    a = fmaf(w.z, h[j + 2], a);
                    a = fmaf(w.w, h[j + 3], a);
                }
                o[ei] = a;
            }
            op[eg] = make_float4(o[0], o[1], o[2], o[3]);
        }
    }
}

extern "C" void kernel_launch(void* const* d_in, const int* in_sizes, int n_in,
                              void* d_out, int out_size) {
    const float* x  = (const float*)d_in[0];
    const float* Qw = (const float*)d_in[1];
    const float* W1 = (const float*)d_in[2];
    const float* b1 = (const float*)d_in[3];
    const float* W2 = (const float*)d_in[4];
    const float* b2 = (const float*)d_in[5];
    float* out = (float*)d_out;

    constexpr int TA = 4;
    constexpr int TB = 4;
    k_zero_sumsq<<<(B_ * E_ + 255) / 256, 256>>>();
    k_passA<TA><<<dim3(S_ / (256 * TA), B_), 256>>>(x, Qw);
    k_passB<TB><<<dim3(S_ / (256 * TB), B_), 256>>>(W1, b1, W2, b2, out);
}

// round 5
// speedup vs baseline: 3.3581x; 3.3581x over previous
#include <cuda_runtime.h>

#define B_ 64
#define S_ 8192
#define E_ 32
#define H_ 64
#define T_ 64                 // tokens per tile
#define TILES_ (S_ / T_)      // 128
#define TP_ 68                // padded row stride (floats) for [.][T_] shared tiles

// Scratch (no allocs allowed): q tensor, tile-transposed layout [b][tile][f][T_].
__device__ __align__(16) static float g_q[(size_t)B_ * S_ * E_];
__device__ static float g_sumsq[B_ * E_];

__global__ void k_zero_sumsq() {
    int i = blockIdx.x * blockDim.x + threadIdx.x;
    if (i < B_ * E_) g_sumsq[i] = 0.0f;
}

__device__ __forceinline__ float silu_f(float v) {
    return v * __fdividef(1.0f, 1.0f + __expf(-v));  // ~1e-7 rel err, budget is 1e-3
}

// ---------------- Pass A: q = silu(x @ Qw^T); accumulate sum_s q^2 ----------------
__global__ __launch_bounds__(256) void k_passA(const float* __restrict__ x,
                                               const float* __restrict__ Qw) {
    const int b = blockIdx.y, tile = blockIdx.x;
    const int tid = threadIdx.x, lane = tid & 31, wy = tid >> 5;
    __shared__ __align__(16) float Qt[E_ * E_];   // [e][f]
    __shared__ __align__(16) float xs[E_ * TP_];  // [e][t], padded

    // Qw [f][e] -> Qt[e][f]
    for (int i = tid; i < E_ * E_; i += 256) Qt[(i & 31) * E_ + (i >> 5)] = Qw[i];

    // x tile [t][e] -> xs[e][t] (coalesced LDG.128, scalar transposed STS)
    const float4* xg = reinterpret_cast<const float4*>(x + ((size_t)b * S_ + tile * T_) * E_);
    for (int i = tid; i < T_ * E_ / 4; i += 256) {
        float4 v = xg[i];
        int t = i >> 3, e = (i & 7) * 4;
        xs[(e + 0) * TP_ + t] = v.x;
        xs[(e + 1) * TP_ + t] = v.y;
        xs[(e + 2) * TP_ + t] = v.z;
        xs[(e + 3) * TP_ + t] = v.w;
    }
    __syncthreads();

    // Register tile: 2 tokens x 4 f per thread (8 warps x 4f = 32 f)
    const int t0 = lane * 2, f0 = wy * 4;
    float a00 = 0, a01 = 0, a10 = 0, a11 = 0, a20 = 0, a21 = 0, a30 = 0, a31 = 0;
#pragma unroll
    for (int e = 0; e < E_; ++e) {
        float2 q = *reinterpret_cast<const float2*>(&xs[e * TP_ + t0]);
        float4 w = *reinterpret_cast<const float4*>(&Qt[e * E_ + f0]);  // broadcast
        a00 = fmaf(w.x, q.x, a00); a01 = fmaf(w.x, q.y, a01);
        a10 = fmaf(w.y, q.x, a10); a11 = fmaf(w.y, q.y, a11);
        a20 = fmaf(w.z, q.x, a20); a21 = fmaf(w.z, q.y, a21);
        a30 = fmaf(w.w, q.x, a30); a31 = fmaf(w.w, q.y, a31);
    }

    float ss[4];
    float* qbase = g_q + (((size_t)b * TILES_ + tile) * E_ + f0) * T_ + t0;
    {
        float v0, v1;
        v0 = silu_f(a00); v1 = silu_f(a01); ss[0] = v0 * v0 + v1 * v1;
        *reinterpret_cast<float2*>(qbase + 0 * T_) = make_float2(v0, v1);
        v0 = silu_f(a10); v1 = silu_f(a11); ss[1] = v0 * v0 + v1 * v1;
        *reinterpret_cast<float2*>(qbase + 1 * T_) = make_float2(v0, v1);
        v0 = silu_f(a20); v1 = silu_f(a21); ss[2] = v0 * v0 + v1 * v1;
        *reinterpret_cast<float2*>(qbase + 2 * T_) = make_float2(v0, v1);
        v0 = silu_f(a30); v1 = silu_f(a31); ss[3] = v0 * v0 + v1 * v1;
        *reinterpret_cast<float2*>(qbase + 3 * T_) = make_float2(v0, v1);
    }
    // Warp-reduce sumsq over the 32 lanes (= 64 tokens), then 4 atomics per warp
#pragma unroll
    for (int fi = 0; fi < 4; ++fi) {
#pragma unroll
        for (int o = 16; o > 0; o >>= 1) ss[fi] += __shfl_xor_sync(0xffffffffu, ss[fi], o);
    }
    if (lane == 0) {
#pragma unroll
        for (int fi = 0; fi < 4; ++fi) atomicAdd(&g_sumsq[b * E_ + f0 + fi], ss[fi]);
    }
}

// ---------------- Pass B: normalize (folded into W1), MLP, write out ----------------
__global__ __launch_bounds__(256) void k_passB(const float* __restrict__ W1,
                                               const float* __restrict__ b1,
                                               const float* __restrict__ W2,
                                               const float* __restrict__ b2,
                                               float* __restrict__ out) {
    const int b = blockIdx.y, tile = blockIdx.x;
    const int tid = threadIdx.x, lane = tid & 31, wy = tid >> 5;
    __shared__ __align__(16) float W1t[E_ * H_];  // [e][j], scaled by 1/norm[e]
    __shared__ __align__(16) float W2t[H_ * E_];  // [j][e]
    __shared__ __align__(16) float qs[E_ * TP_];  // [e][t]
    __shared__ __align__(16) float hs[H_ * TP_];  // [j][t]
    __shared__ float b1s[H_], b2s[E_], rsq[E_];

    if (tid < E_) {
        float n = sqrtf(g_sumsq[b * E_ + tid]);
        rsq[tid] = 1.0f / fmaxf(n, 1e-12f);
        b2s[tid] = b2[b * E_ + tid];
    }
    if (tid < H_) b1s[tid] = b1[b * H_ + tid];
    __syncthreads();

    // W1 [j][e] -> W1t[e][j] * rsq[e];  W2 [e][j] -> W2t[j][e]
    const size_t wbase = (size_t)b * H_ * E_;
    for (int i = tid; i < H_ * E_; i += 256) {
        int j = i >> 5, e = i & 31;
        W1t[e * H_ + j] = W1[wbase + i] * rsq[e];
    }
    for (int i = tid; i < E_ * H_; i += 256) {
        int e = i >> 6, j = i & 63;
        W2t[j * E_ + e] = W2[wbase + i];
    }
    // q tile already [e][t]: straight vector copy into padded shared
    const float4* qg = reinterpret_cast<const float4*>(
        g_q + ((size_t)b * TILES_ + tile) * E_ * T_);
    for (int i = tid; i < E_ * T_ / 4; i += 256) {
        float4 v = qg[i];
        int e = i >> 4, t4 = (i & 15) * 4;
        *reinterpret_cast<float4*>(&qs[e * TP_ + t4]) = v;
    }
    __syncthreads();

    const int t0 = lane * 2;

    // ---- GEMM1: h[j][t] = silu(q @ W1t + b1); 2 tokens x 8 j per thread ----
    {
        const int j0 = wy * 8;
        float acc[8][2];
#pragma unroll
        for (int ji = 0; ji < 8; ++ji) acc[ji][0] = acc[ji][1] = b1s[j0 + ji];
#pragma unroll
        for (int e = 0; e < E_; ++e) {
            float2 q = *reinterpret_cast<const float2*>(&qs[e * TP_ + t0]);
            float4 wa = *reinterpret_cast<const float4*>(&W1t[e * H_ + j0]);
            float4 wb = *reinterpret_cast<const float4*>(&W1t[e * H_ + j0 + 4]);
            acc[0][0] = fmaf(wa.x, q.x, acc[0][0]); acc[0][1] = fmaf(wa.x, q.y, acc[0][1]);
            acc[1][0] = fmaf(wa.y, q.x, acc[1][0]); acc[1][1] = fmaf(wa.y, q.y, acc[1][1]);
            acc[2][0] = fmaf(wa.z, q.x, acc[2][0]); acc[2][1] = fmaf(wa.z, q.y, acc[2][1]);
            acc[3][0] = fmaf(wa.w, q.x, acc[3][0]); acc[3][1] = fmaf(wa.w, q.y, acc[3][1]);
            acc[4][0] = fmaf(wb.x, q.x, acc[4][0]); acc[4][1] = fmaf(wb.x, q.y, acc[4][1]);
            acc[5][0] = fmaf(wb.y, q.x, acc[5][0]); acc[5][1] = fmaf(wb.y, q.y, acc[5][1]);
            acc[6][0] = fmaf(wb.z, q.x, acc[6][0]); acc[6][1] = fmaf(wb.z, q.y, acc[6][1]);
            acc[7][0] = fmaf(wb.w, q.x, acc[7][0]); acc[7][1] = fmaf(wb.w, q.y, acc[7][1]);
        }
#pragma unroll
        for (int ji = 0; ji < 8; ++ji) {
            *reinterpret_cast<float2*>(&hs[(j0 + ji) * TP_ + t0]) =
                make_float2(silu_f(acc[ji][0]), silu_f(acc[ji][1]));
        }
    }
    __syncthreads();

    // ---- GEMM2: out[t][e] = h @ W2t + b2; 2 tokens x 4 e per thread ----
    {
        const int e0 = wy * 4;
        float o[4][2];
#pragma unroll
        for (int ei = 0; ei < 4; ++ei) o[ei][0] = o[ei][1] = b2s[e0 + ei];
#pragma unroll
        for (int j = 0; j < H_; ++j) {
            float2 h = *reinterpret_cast<const float2*>(&hs[j * TP_ + t0]);
            float4 w = *reinterpret_cast<const float4*>(&W2t[j * E_ + e0]);
            o[0][0] = fmaf(w.x, h.x, o[0][0]); o[0][1] = fmaf(w.x, h.y, o[0][1]);
            o[1][0] = fmaf(w.y, h.x, o[1][0]); o[1][1] = fmaf(w.y, h.y, o[1][1]);
            o[2][0] = fmaf(w.z, h.x, o[2][0]); o[2][1] = fmaf(w.z, h.y, o[2][1]);
            o[3][0] = fmaf(w.w, h.x, o[3][0]); o[3][1] = fmaf(w.w, h.y, o[3][1]);
        }
        float* ob = out + ((size_t)b * S_ + tile * T_ + t0) * E_ + e0;
        *reinterpret_cast<float4*>(ob)      = make_float4(o[0][0], o[1][0], o[2][0], o[3][0]);
        *reinterpret_cast<float4*>(ob + E_) = make_float4(o[0][1], o[1][1], o[2][1], o[3][1]);
    }
}

extern "C" void kernel_launch(void* const* d_in, const int* in_sizes, int n_in,
                              void* d_out, int out_size) {
    const float* x  = (const float*)d_in[0];
    const float* Qw = (const float*)d_in[1];
    const float* W1 = (const float*)d_in[2];
    const float* b1 = (const float*)d_in[3];
    const float* W2 = (const float*)d_in[4];
    const float* b2 = (const float*)d_in[5];
    float* out = (float*)d_out;

    k_zero_sumsq<<<(B_ * E_ + 255) / 256, 256>>>();
    k_passA<<<dim3(TILES_, B_), 256>>>(x, Qw);
    k_passB<<<dim3(TILES_, B_), 256>>>(W1, b1, W2, b2, out);
}

// round 7
// speedup vs baseline: 5.1872x; 1.5447x over previous
#include <cuda_runtime.h>

#define B_ 64
#define S_ 8192
#define E_ 32
#define H_ 64
#define T_ 64                  // tokens per tile
#define TILES_ (S_ / T_)       // 128
#define TPA_ 4                 // tiles per pass-A block
#define TPB_ 4                 // tiles per pass-B block
#define NBA_ (TILES_ / TPA_)   // 32 pass-A blocks per batch row
#define TP_ 68                 // padded token stride in shared

typedef unsigned long long u64;

// Scratch: q in [b][tile][f][T_] layout + per-block sumsq partials.
__device__ __align__(16) static float g_q[(size_t)B_ * S_ * E_];
__device__ static float g_part[B_ * NBA_ * E_];

__device__ __forceinline__ u64 pack2(float lo, float hi) {
    u64 r; asm("mov.b64 %0, {%1,%2};" : "=l"(r) : "f"(lo), "f"(hi)); return r;
}
__device__ __forceinline__ float2 unpack2(u64 v) {
    float2 f; asm("mov.b64 {%0,%1}, %2;" : "=f"(f.x), "=f"(f.y) : "l"(v)); return f;
}
__device__ __forceinline__ u64 ffma2(u64 a, u64 b, u64 c) {
    u64 d; asm("fma.rn.f32x2 %0, %1, %2, %3;" : "=l"(d) : "l"(a), "l"(b), "l"(c));
    return d;
}
__device__ __forceinline__ float silu_f(float v) {
    return v * __fdividef(1.0f, 1.0f + __expf(-v));  // ~1e-7 rel err; budget 1e-3
}

// ---------------- Pass A: q = silu(x @ Qw^T); per-block sumsq partials ----------------
__global__ __launch_bounds__(256) void k_passA(const float* __restrict__ x,
                                               const float* __restrict__ Qw) {
    const int b = blockIdx.y, bx = blockIdx.x;
    const int tid = threadIdx.x, lane = tid & 31, wy = tid >> 5;
    __shared__ __align__(16) float Qt[E_ * E_];   // [e][f]
    __shared__ __align__(16) float xs[E_ * TP_];  // [e][t]

    // Qt fill: lane carries f -> conflict-free STS; LDG scattered (tiny, L2-hot)
    {
        int f = tid & 31, eg = tid >> 5;
        for (int e = eg; e < E_; e += 8) Qt[e * E_ + f] = Qw[f * E_ + e];
    }

    const int t0 = lane * 2, f0 = wy * 4;
    float ss[4] = {0.f, 0.f, 0.f, 0.f};

    for (int tt = 0; tt < TPA_; ++tt) {
        const int tile = bx * TPA_ + tt;
        __syncthreads();  // xs readers of previous iter done (also covers Qt on tt=0)
        const float4* xg = reinterpret_cast<const float4*>(
            x + ((size_t)b * S_ + tile * T_) * E_);
        for (int i = tid; i < T_ * E_ / 4; i += 256) {
            float4 v = xg[i];
            int t = i >> 3, e = (i & 7) * 4;
            xs[(e + 0) * TP_ + t] = v.x;
            xs[(e + 1) * TP_ + t] = v.y;
            xs[(e + 2) * TP_ + t] = v.z;
            xs[(e + 3) * TP_ + t] = v.w;
        }
        __syncthreads();

        // acc[fp][ti]: f-pair (f0+2fp, f0+2fp+1) packed, token ti
        u64 acc[2][2];
        acc[0][0] = acc[0][1] = acc[1][0] = acc[1][1] = 0ull;
#pragma unroll
        for (int e = 0; e < E_; ++e) {
            float2 q = *reinterpret_cast<const float2*>(&xs[e * TP_ + t0]);
            u64 qb0 = pack2(q.x, q.x), qb1 = pack2(q.y, q.y);
            ulonglong2 w = *reinterpret_cast<const ulonglong2*>(&Qt[e * E_ + f0]);
            acc[0][0] = ffma2(w.x, qb0, acc[0][0]);
            acc[0][1] = ffma2(w.x, qb1, acc[0][1]);
            acc[1][0] = ffma2(w.y, qb0, acc[1][0]);
            acc[1][1] = ffma2(w.y, qb1, acc[1][1]);
        }

        float* qb = g_q + (((size_t)b * TILES_ + tile) * E_ + f0) * T_ + t0;
#pragma unroll
        for (int fp = 0; fp < 2; ++fp) {
            float2 a0 = unpack2(acc[fp][0]);  // (f_lo,f_hi) @ t0
            float2 a1 = unpack2(acc[fp][1]);  // (f_lo,f_hi) @ t0+1
            float vlo0 = silu_f(a0.x), vlo1 = silu_f(a1.x);
            float vhi0 = silu_f(a0.y), vhi1 = silu_f(a1.y);
            *reinterpret_cast<float2*>(qb + (2 * fp + 0) * T_) = make_float2(vlo0, vlo1);
            *reinterpret_cast<float2*>(qb + (2 * fp + 1) * T_) = make_float2(vhi0, vhi1);
            ss[2 * fp + 0] += vlo0 * vlo0 + vlo1 * vlo1;
            ss[2 * fp + 1] += vhi0 * vhi0 + vhi1 * vhi1;
        }
    }

    // Warp-reduce over lanes (tokens); per-block partial write, no atomics
#pragma unroll
    for (int i = 0; i < 4; ++i) {
#pragma unroll
        for (int o = 16; o > 0; o >>= 1) ss[i] += __shfl_xor_sync(0xffffffffu, ss[i], o);
    }
    if (lane == 0) {
#pragma unroll
        for (int i = 0; i < 4; ++i)
            g_part[(b * NBA_ + bx) * E_ + f0 + i] = ss[i];
    }
}

// ---------------- Pass B: reduce norm, fold into W1, MLP, write out ----------------
__global__ __launch_bounds__(256) void k_passB(const float* __restrict__ W1,
                                               const float* __restrict__ b1,
                                               const float* __restrict__ W2,
                                               const float* __restrict__ b2,
                                               float* __restrict__ out) {
    const int b = blockIdx.y, bx = blockIdx.x;
    const int tid = threadIdx.x, lane = tid & 31, wy = tid >> 5;
    __shared__ __align__(16) float W1t[E_ * H_];  // [e][j], scaled by 1/norm[e]
    __shared__ __align__(16) float W2t[H_ * E_];  // [j][e]
    __shared__ __align__(16) float qs[E_ * TP_];  // [e][t]
    __shared__ __align__(16) float hs[H_ * TP_];  // [j][t]
    __shared__ __align__(8) float b1s[H_];
    __shared__ __align__(8) float b2s[E_];
    __shared__ float rsq[E_];

    if (tid < E_) {
        float s = 0.f;
#pragma unroll
        for (int k = 0; k < NBA_; ++k) s += g_part[(b * NBA_ + k) * E_ + tid];
        rsq[tid] = 1.0f / fmaxf(sqrtf(s), 1e-12f);
        b2s[tid] = b2[b * E_ + tid];
    }
    if (tid < H_) b1s[tid] = b1[b * H_ + tid];
    __syncthreads();

    // Conflict-free transposed fills: lane carries the bank-varying index
    const size_t wbase = (size_t)b * H_ * E_;
    {
        int j = tid & 63, eg = tid >> 6;
        for (int e = eg; e < E_; e += 4)
            W1t[e * H_ + j] = W1[wbase + j * E_ + e] * rsq[e];
    }
    {
        int e = tid & 31, jg = tid >> 5;
        for (int j = jg; j < H_; j += 8)
            W2t[j * E_ + e] = W2[wbase + e * H_ + j];
    }

    for (int tt = 0; tt < TPB_; ++tt) {
        const int tile = bx * TPB_ + tt;
        __syncthreads();  // prior-iter qs/hs readers done (covers weight fills on tt=0)
        const float4* qg = reinterpret_cast<const float4*>(
            g_q + ((size_t)b * TILES_ + tile) * E_ * T_);
        for (int i = tid; i < E_ * T_ / 4; i += 256) {
            float4 v = qg[i];
            int e = i >> 4, t4 = (i & 15) * 4;
            *reinterpret_cast<float4*>(&qs[e * TP_ + t4]) = v;
        }
        __syncthreads();

        // ---- GEMM1: 4 j-pairs x 2 tokens per thread, f32x2 over j-pairs ----
        {
            const int j0 = wy * 8, t0 = lane * 2;
            u64 hacc[4][2];
#pragma unroll
            for (int jp = 0; jp < 4; ++jp) {
                u64 bp = *reinterpret_cast<const u64*>(&b1s[j0 + 2 * jp]);
                hacc[jp][0] = bp; hacc[jp][1] = bp;
            }
#pragma unroll
            for (int e = 0; e < E_; ++e) {
                float2 q = *reinterpret_cast<const float2*>(&qs[e * TP_ + t0]);
                u64 qb0 = pack2(q.x, q.x), qb1 = pack2(q.y, q.y);
                ulonglong2 wa = *reinterpret_cast<const ulonglong2*>(&W1t[e * H_ + j0]);
                ulonglong2 wb = *reinterpret_cast<const ulonglong2*>(&W1t[e * H_ + j0 + 4]);
                hacc[0][0] = ffma2(wa.x, qb0, hacc[0][0]);
                hacc[0][1] = ffma2(wa.x, qb1, hacc[0][1]);
                hacc[1][0] = ffma2(wa.y, qb0, hacc[1][0]);
                hacc[1][1] = ffma2(wa.y, qb1, hacc[1][1]);
                hacc[2][0] = ffma2(wb.x, qb0, hacc[2][0]);
                hacc[2][1] = ffma2(wb.x, qb1, hacc[2][1]);
                hacc[3][0] = ffma2(wb.y, qb0, hacc[3][0]);
                hacc[3][1] = ffma2(wb.y, qb1, hacc[3][1]);
            }
#pragma unroll
            for (int jp = 0; jp < 4; ++jp) {
                float2 a0 = unpack2(hacc[jp][0]);  // (j_lo,j_hi) @ t0
                float2 a1 = unpack2(hacc[jp][1]);  // (j_lo,j_hi) @ t0+1
                *reinterpret_cast<float2*>(&hs[(j0 + 2 * jp + 0) * TP_ + t0]) =
                    make_float2(silu_f(a0.x), silu_f(a1.x));
                *reinterpret_cast<float2*>(&hs[(j0 + 2 * jp + 1) * TP_ + t0]) =
                    make_float2(silu_f(a0.y), silu_f(a1.y));
            }
        }
        __syncthreads();

        // ---- GEMM2: 2 e-pairs x 2 tokens; token-major mapping for coalesced STG ----
        {
            const int tk = tid >> 3;            // token pair index (0..31)
            const int ec = (tid & 7) * 4;       // e chunk
            u64 oacc[2][2];
#pragma unroll
            for (int ep = 0; ep < 2; ++ep) {
                u64 bp = *reinterpret_cast<const u64*>(&b2s[ec + 2 * ep]);
                oacc[ep][0] = bp; oacc[ep][1] = bp;
            }
#pragma unroll
            for (int j = 0; j < H_; ++j) {
                float2 h = *reinterpret_cast<const float2*>(&hs[j * TP_ + 2 * tk]);
                u64 hb0 = pack2(h.x, h.x), hb1 = pack2(h.y, h.y);
                ulonglong2 w = *reinterpret_cast<const ulonglong2*>(&W2t[j * E_ + ec]);
                oacc[0][0] = ffma2(w.x, hb0, oacc[0][0]);
                oacc[0][1] = ffma2(w.x, hb1, oacc[0][1]);
                oacc[1][0] = ffma2(w.y, hb0, oacc[1][0]);
                oacc[1][1] = ffma2(w.y, hb1, oacc[1][1]);
            }
            float* ob = out + ((size_t)b * S_ + tile * T_ + 2 * tk) * E_ + ec;
            float2 u00 = unpack2(oacc[0][0]), u10 = unpack2(oacc[1][0]);
            float2 u01 = unpack2(oacc[0][1]), u11 = unpack2(oacc[1][1]);
            *reinterpret_cast<float4*>(ob)      = make_float4(u00.x, u00.y, u10.x, u10.y);
            *reinterpret_cast<float4*>(ob + E_) = make_float4(u01.x, u01.y, u11.x, u11.y);
        }
    }
}

extern "C" void kernel_launch(void* const* d_in, const int* in_sizes, int n_in,
                              void* d_out, int out_size) {
    const float* x  = (const float*)d_in[0];
    const float* Qw = (const float*)d_in[1];
    const float* W1 = (const float*)d_in[2];
    const float* b1 = (const float*)d_in[3];
    const float* W2 = (const float*)d_in[4];
    const float* b2 = (const float*)d_in[5];
    float* out = (float*)d_out;

    k_passA<<<dim3(NBA_, B_), 256>>>(x, Qw);
    k_passB<<<dim3(TILES_ / TPB_, B_), 256>>>(W1, b1, W2, b2, out);
}

// round 8
// speedup vs baseline: 6.6290x; 1.2780x over previous
#include <cuda_runtime.h>

#define B_ 64
#define S_ 8192
#define E_ 32
#define H_ 64
#define T_ 128                 // tokens per tile
#define TILES_ (S_ / T_)       // 64
#define TPA_ 4                 // tiles per pass-A block
#define TPB_ 4                 // tiles per pass-B block
#define NBA_ (TILES_ / TPA_)   // 16 pass-A blocks per batch row
#define XP_ 132                // padded token stride for pass-A xs only

typedef unsigned long long u64;

// Scratch: q in [b][tile][e][T_] layout + per-block sumsq partials.
__device__ __align__(16) static float g_q[(size_t)B_ * S_ * E_];
__device__ static float g_part[B_ * NBA_ * E_];

__device__ __forceinline__ u64 pack2(float lo, float hi) {
    u64 r; asm("mov.b64 %0, {%1,%2};" : "=l"(r) : "f"(lo), "f"(hi)); return r;
}
__device__ __forceinline__ float2 unpack2(u64 v) {
    float2 f; asm("mov.b64 {%0,%1}, %2;" : "=f"(f.x), "=f"(f.y) : "l"(v)); return f;
}
__device__ __forceinline__ u64 ffma2(u64 a, u64 b, u64 c) {
    u64 d; asm("fma.rn.f32x2 %0, %1, %2, %3;" : "=l"(d) : "l"(a), "l"(b), "l"(c));
    return d;
}
__device__ __forceinline__ float silu_f(float v) {
    return v * __fdividef(1.0f, 1.0f + __expf(-v));  // ~1e-7 rel err; budget 1e-3
}

// ---------------- Pass A: q = silu(x @ Qw^T); per-block sumsq partials ----------------
__global__ __launch_bounds__(256) void k_passA(const float* __restrict__ x,
                                               const float* __restrict__ Qw) {
    const int b = blockIdx.y, bx = blockIdx.x;
    const int tid = threadIdx.x, lane = tid & 31, wy = tid >> 5;
    __shared__ __align__(16) float Qt[E_ * E_];   // [e][f]
    __shared__ __align__(16) float xs[E_ * XP_];  // [e][t], padded

    {   // conflict-free transposed fill: lane carries f
        int f = tid & 31, eg = tid >> 5;
        for (int e = eg; e < E_; e += 8) Qt[e * E_ + f] = Qw[f * E_ + e];
    }

    const int t0 = lane * 4, f0 = wy * 4;
    float ss[4] = {0.f, 0.f, 0.f, 0.f};

    for (int tt = 0; tt < TPA_; ++tt) {
        const int tile = bx * TPA_ + tt;
        __syncthreads();  // prior-iter xs readers done (covers Qt on tt=0)
        const float4* xg = reinterpret_cast<const float4*>(
            x + ((size_t)b * S_ + tile * T_) * E_);
        for (int i = tid; i < T_ * E_ / 4; i += 256) {
            float4 v = xg[i];
            int t = i >> 3, e = (i & 7) * 4;
            xs[(e + 0) * XP_ + t] = v.x;
            xs[(e + 1) * XP_ + t] = v.y;
            xs[(e + 2) * XP_ + t] = v.z;
            xs[(e + 3) * XP_ + t] = v.w;
        }
        __syncthreads();

        // acc[fp][t]: f-pair fp packed, token t (2 f-pairs x 4 tokens)
        u64 acc[2][4];
#pragma unroll
        for (int fp = 0; fp < 2; ++fp)
#pragma unroll
            for (int t = 0; t < 4; ++t) acc[fp][t] = 0ull;

#pragma unroll
        for (int e = 0; e < E_; ++e) {
            float4 q = *reinterpret_cast<const float4*>(&xs[e * XP_ + t0]);
            u64 qb0 = pack2(q.x, q.x), qb1 = pack2(q.y, q.y);
            u64 qb2 = pack2(q.z, q.z), qb3 = pack2(q.w, q.w);
            ulonglong2 w = *reinterpret_cast<const ulonglong2*>(&Qt[e * E_ + f0]);
            acc[0][0] = ffma2(w.x, qb0, acc[0][0]);
            acc[0][1] = ffma2(w.x, qb1, acc[0][1]);
            acc[0][2] = ffma2(w.x, qb2, acc[0][2]);
            acc[0][3] = ffma2(w.x, qb3, acc[0][3]);
            acc[1][0] = ffma2(w.y, qb0, acc[1][0]);
            acc[1][1] = ffma2(w.y, qb1, acc[1][1]);
            acc[1][2] = ffma2(w.y, qb2, acc[1][2]);
            acc[1][3] = ffma2(w.y, qb3, acc[1][3]);
        }

        float* qb = g_q + (((size_t)b * TILES_ + tile) * E_ + f0) * T_ + t0;
#pragma unroll
        for (int fp = 0; fp < 2; ++fp) {
            float2 a0 = unpack2(acc[fp][0]), a1 = unpack2(acc[fp][1]);
            float2 a2 = unpack2(acc[fp][2]), a3 = unpack2(acc[fp][3]);
            float l0 = silu_f(a0.x), l1 = silu_f(a1.x), l2 = silu_f(a2.x), l3 = silu_f(a3.x);
            float h0 = silu_f(a0.y), h1 = silu_f(a1.y), h2 = silu_f(a2.y), h3 = silu_f(a3.y);
            *reinterpret_cast<float4*>(qb + (2 * fp + 0) * T_) = make_float4(l0, l1, l2, l3);
            *reinterpret_cast<float4*>(qb + (2 * fp + 1) * T_) = make_float4(h0, h1, h2, h3);
            ss[2 * fp + 0] += l0 * l0 + l1 * l1 + l2 * l2 + l3 * l3;
            ss[2 * fp + 1] += h0 * h0 + h1 * h1 + h2 * h2 + h3 * h3;
        }
    }

#pragma unroll
    for (int i = 0; i < 4; ++i) {
#pragma unroll
        for (int o = 16; o > 0; o >>= 1) ss[i] += __shfl_xor_sync(0xffffffffu, ss[i], o);
    }
    if (lane == 0) {
#pragma unroll
        for (int i = 0; i < 4; ++i) g_part[(b * NBA_ + bx) * E_ + f0 + i] = ss[i];
    }
}

// ---------------- Pass B: reduce norm, fold into W1, MLP, write out ----------------
// Dynamic smem layout (floats): W1t[0,2048) [e][j] scaled; W2t[2048,4096) [j][e];
// qs[4096,8192) [e][T_]; hs[8192,16384) [j][T_].
__global__ __launch_bounds__(256, 3) void k_passB(const float* __restrict__ W1,
                                                  const float* __restrict__ b1,
                                                  const float* __restrict__ W2,
                                                  const float* __restrict__ b2,
                                                  float* __restrict__ out) {
    extern __shared__ __align__(16) float sm[];
    float* W1t = sm;
    float* W2t = sm + 2048;
    float* qs  = sm + 4096;
    float* hs  = sm + 8192;
    __shared__ __align__(8) float b1s[H_];
    __shared__ __align__(8) float b2s[E_];
    __shared__ float rsq[E_];

    const int b = blockIdx.y, bx = blockIdx.x;
    const int tid = threadIdx.x, lane = tid & 31, wy = tid >> 5;

    if (tid < E_) {
        float s = 0.f;
#pragma unroll
        for (int k = 0; k < NBA_; ++k) s += g_part[(b * NBA_ + k) * E_ + tid];
        rsq[tid] = 1.0f / fmaxf(sqrtf(s), 1e-12f);
        b2s[tid] = b2[b * E_ + tid];
    }
    if (tid < H_) b1s[tid] = b1[b * H_ + tid];
    __syncthreads();

    // Conflict-free transposed weight fills: lane carries the bank-varying index
    const size_t wbase = (size_t)b * H_ * E_;
    {
        int j = tid & 63, eg = tid >> 6;
        for (int e = eg; e < E_; e += 4)
            W1t[e * H_ + j] = W1[wbase + j * E_ + e] * rsq[e];
    }
    {
        int e = tid & 31, jg = tid >> 5;
        for (int j = jg; j < H_; j += 8)
            W2t[j * E_ + e] = W2[wbase + e * H_ + j];
    }

    for (int tt = 0; tt < TPB_; ++tt) {
        const int tile = bx * TPB_ + tt;
        __syncthreads();  // prior-iter qs/hs readers done (covers weight fills on tt=0)
        const float4* qg = reinterpret_cast<const float4*>(
            g_q + ((size_t)b * TILES_ + tile) * E_ * T_);
        for (int i = tid; i < E_ * T_ / 4; i += 256)
            reinterpret_cast<float4*>(qs)[i] = qg[i];  // same [e][t] layout, straight copy
        __syncthreads();

        // ---- GEMM1: 4 j-pairs x 4 tokens per thread ----
        {
            const int j0 = wy * 8, t0 = lane * 4;
            u64 hacc[4][4];
#pragma unroll
            for (int jp = 0; jp < 4; ++jp) {
                u64 bp = *reinterpret_cast<const u64*>(&b1s[j0 + 2 * jp]);
#pragma unroll
                for (int t = 0; t < 4; ++t) hacc[jp][t] = bp;
            }
#pragma unroll
            for (int e = 0; e < E_; ++e) {
                float4 q = *reinterpret_cast<const float4*>(&qs[e * T_ + t0]);
                u64 qb0 = pack2(q.x, q.x), qb1 = pack2(q.y, q.y);
                u64 qb2 = pack2(q.z, q.z), qb3 = pack2(q.w, q.w);
                ulonglong2 wa = *reinterpret_cast<const ulonglong2*>(&W1t[e * H_ + j0]);
                ulonglong2 wb = *reinterpret_cast<const ulonglong2*>(&W1t[e * H_ + j0 + 4]);
                hacc[0][0] = ffma2(wa.x, qb0, hacc[0][0]);
                hacc[0][1] = ffma2(wa.x, qb1, hacc[0][1]);
                hacc[0][2] = ffma2(wa.x, qb2, hacc[0][2]);
                hacc[0][3] = ffma2(wa.x, qb3, hacc[0][3]);
                hacc[1][0] = ffma2(wa.y, qb0, hacc[1][0]);
                hacc[1][1] = ffma2(wa.y, qb1, hacc[1][1]);
                hacc[1][2] = ffma2(wa.y, qb2, hacc[1][2]);
                hacc[1][3] = ffma2(wa.y, qb3, hacc[1][3]);
                hacc[2][0] = ffma2(wb.x, qb0, hacc[2][0]);
                hacc[2][1] = ffma2(wb.x, qb1, hacc[2][1]);
                hacc[2][2] = ffma2(wb.x, qb2, hacc[2][2]);
                hacc[2][3] = ffma2(wb.x, qb3, hacc[2][3]);
                hacc[3][0] = ffma2(wb.y, qb0, hacc[3][0]);
                hacc[3][1] = ffma2(wb.y, qb1, hacc[3][1]);
                hacc[3][2] = ffma2(wb.y, qb2, hacc[3][2]);
                hacc[3][3] = ffma2(wb.y, qb3, hacc[3][3]);
            }
#pragma unroll
            for (int jp = 0; jp < 4; ++jp) {
                float2 a0 = unpack2(hacc[jp][0]), a1 = unpack2(hacc[jp][1]);
                float2 a2 = unpack2(hacc[jp][2]), a3 = unpack2(hacc[jp][3]);
                *reinterpret_cast<float4*>(&hs[(j0 + 2 * jp + 0) * T_ + t0]) =
                    make_float4(silu_f(a0.x), silu_f(a1.x), silu_f(a2.x), silu_f(a3.x));
                *reinterpret_cast<float4*>(&hs[(j0 + 2 * jp + 1) * T_ + t0]) =
                    make_float4(silu_f(a0.y), silu_f(a1.y), silu_f(a2.y), silu_f(a3.y));
            }
        }
        __syncthreads();

        // ---- GEMM2: 2 e-pairs x 4 tokens per thread; coalesced STG rows ----
        {
            const int tg = tid >> 3;        // token group (0..31) -> 4 tokens
            const int ec = (tid & 7) * 4;   // e chunk
            const int t0 = tg * 4;
            u64 oacc[2][4];
#pragma unroll
            for (int ep = 0; ep < 2; ++ep) {
                u64 bp = *reinterpret_cast<const u64*>(&b2s[ec + 2 * ep]);
#pragma unroll
                for (int t = 0; t < 4; ++t) oacc[ep][t] = bp;
            }
#pragma unroll
            for (int j = 0; j < H_; ++j) {
                float4 h = *reinterpret_cast<const float4*>(&hs[j * T_ + t0]);
                u64 hb0 = pack2(h.x, h.x), hb1 = pack2(h.y, h.y);
                u64 hb2 = pack2(h.z, h.z), hb3 = pack2(h.w, h.w);
                ulonglong2 w = *reinterpret_cast<const ulonglong2*>(&W2t[j * E_ + ec]);
                oacc[0][0] = ffma2(w.x, hb0, oacc[0][0]);
                oacc[0][1] = ffma2(w.x, hb1, oacc[0][1]);
                oacc[0][2] = ffma2(w.x, hb2, oacc[0][2]);
                oacc[0][3] = ffma2(w.x, hb3, oacc[0][3]);
                oacc[1][0] = ffma2(w.y, hb0, oacc[1][0]);
                oacc[1][1] = ffma2(w.y, hb1, oacc[1][1]);
                oacc[1][2] = ffma2(w.y, hb2, oacc[1][2]);
                oacc[1][3] = ffma2(w.y, hb3, oacc[1][3]);
            }
            float* ob = out + ((size_t)b * S_ + tile * T_ + t0) * E_ + ec;
#pragma unroll
            for (int t = 0; t < 4; ++t) {
                float2 u0 = unpack2(oacc[0][t]);
                float2 u1 = unpack2(oacc[1][t]);
                *reinterpret_cast<float4*>(ob + t * E_) = make_float4(u0.x, u0.y, u1.x, u1.y);
            }
        }
    }
}

extern "C" void kernel_launch(void* const* d_in, const int* in_sizes, int n_in,
                              void* d_out, int out_size) {
    const float* x  = (const float*)d_in[0];
    const float* Qw = (const float*)d_in[1];
    const float* W1 = (const float*)d_in[2];
    const float* b1 = (const float*)d_in[3];
    const float* W2 = (const float*)d_in[4];
    const float* b2 = (const float*)d_in[5];
    float* out = (float*)d_out;

    const int smemB = 16384 * sizeof(float);  // 64 KB dynamic
    cudaFuncSetAttribute(k_passB, cudaFuncAttributeMaxDynamicSharedMemorySize, smemB);

    k_passA<<<dim3(NBA_, B_), 256>>>(x, Qw);
    k_passB<<<dim3(TILES_ / TPB_, B_), 256, smemB>>>(W1, b1, W2, b2, out);
}